// round 4
// baseline (speedup 1.0000x reference)
#include <cuda_runtime.h>

#define B_SZ 4
#define S_LEN 2048
#define D_MOD 1024
#define H_CNT 16
#define HD 64

// Scratch (allocation-free rule: __device__ globals)
__device__ float g_qkv[(size_t)B_SZ * S_LEN * 3 * D_MOD];   // [B*S, 3D]
__device__ float g_att[(size_t)B_SZ * S_LEN * D_MOD];       // [B*S, D]

// ---------------------------------------------------------------------------
// SGEMM: C[M,N] = A[M,K] * B[K,N], row-major, M%128==0, N%128==0, K%8==0
// 128x128 block tile, BK=8, 256 threads, each thread a 2x2 grid of 4x4 tiles.
// ---------------------------------------------------------------------------
__global__ __launch_bounds__(256) void sgemm_kernel(
    const float* __restrict__ A, const float* __restrict__ B,
    float* __restrict__ C, int M, int N, int K)
{
    __shared__ float As[8][132];   // transposed A tile: As[k][m]
    __shared__ float Bs[8][132];   // Bs[k][n]

    const int tid = threadIdx.x;
    const int tx = tid & 15;
    const int ty = tid >> 4;
    const int m0 = blockIdx.y * 128;
    const int n0 = blockIdx.x * 128;

    const int arow = tid >> 1;          // 0..127
    const int acol = (tid & 1) * 4;     // 0 or 4
    const int brow = tid >> 5;          // 0..7
    const int bcol = (tid & 31) * 4;    // 0..124

    float acc[8][8];
    #pragma unroll
    for (int i = 0; i < 8; i++)
        #pragma unroll
        for (int j = 0; j < 8; j++) acc[i][j] = 0.0f;

    for (int k0 = 0; k0 < K; k0 += 8) {
        float4 av = *(const float4*)(A + (size_t)(m0 + arow) * K + k0 + acol);
        float4 bv = *(const float4*)(B + (size_t)(k0 + brow) * N + n0 + bcol);
        As[acol + 0][arow] = av.x;
        As[acol + 1][arow] = av.y;
        As[acol + 2][arow] = av.z;
        As[acol + 3][arow] = av.w;
        *(float4*)&Bs[brow][bcol] = bv;
        __syncthreads();

        #pragma unroll
        for (int kk = 0; kk < 8; kk++) {
            float4 a0 = *(const float4*)&As[kk][4 * ty];
            float4 a1 = *(const float4*)&As[kk][64 + 4 * ty];
            float4 b0 = *(const float4*)&Bs[kk][4 * tx];
            float4 b1 = *(const float4*)&Bs[kk][64 + 4 * tx];
            float a[8] = {a0.x, a0.y, a0.z, a0.w, a1.x, a1.y, a1.z, a1.w};
            float b[8] = {b0.x, b0.y, b0.z, b0.w, b1.x, b1.y, b1.z, b1.w};
            #pragma unroll
            for (int i = 0; i < 8; i++)
                #pragma unroll
                for (int j = 0; j < 8; j++)
                    acc[i][j] = fmaf(a[i], b[j], acc[i][j]);
        }
        __syncthreads();
    }

    #pragma unroll
    for (int ih = 0; ih < 2; ih++) {
        #pragma unroll
        for (int i = 0; i < 4; i++) {
            int row = m0 + ih * 64 + 4 * ty + i;
            #pragma unroll
            for (int jh = 0; jh < 2; jh++) {
                float4 v = make_float4(acc[ih * 4 + i][jh * 4 + 0],
                                       acc[ih * 4 + i][jh * 4 + 1],
                                       acc[ih * 4 + i][jh * 4 + 2],
                                       acc[ih * 4 + i][jh * 4 + 3]);
                *(float4*)(C + (size_t)row * N + n0 + jh * 64 + 4 * tx) = v;
            }
        }
    }
}

// ---------------------------------------------------------------------------
// Flash attention: one block = one (b, h, 64-query tile).
// smem (stride 65 to keep bank conflicts <= 2-way; all scalar LDS/STS):
//   sQ[d][i] : transposed, pre-scaled Q tile (64x64)
//   sK[j][d] : natural K tile
//   sV[j][c] : natural V tile
//   sP[i][j] : probability tile
// 256 threads as 16x16; thread (tx,ty) owns score/O rows 4ty..4ty+3,
// cols 4tx..4tx+3. Row softmax stats replicated across tx -> shfl.bfly only.
// ---------------------------------------------------------------------------
#define LDQ(d, i) sQ[(d) * 65 + (i)]
#define LDK(j, d) sK[(j) * 65 + (d)]
#define LDV(j, c) sV[(j) * 65 + (c)]
#define LDP(i, j) sP[(i) * 65 + (j)]

extern __shared__ float attn_smem[];

__global__ __launch_bounds__(256) void attn_kernel()
{
    float* sQ = attn_smem;
    float* sK = attn_smem + 64 * 65;
    float* sV = attn_smem + 2 * 64 * 65;
    float* sP = attn_smem + 3 * 64 * 65;

    const int tid = threadIdx.x;
    const int tx = tid & 15;
    const int ty = tid >> 4;
    const int bh = blockIdx.y;
    const int b = bh >> 4;
    const int h = bh & 15;
    const int q0 = blockIdx.x * 64;

    const float scale = 0.125f;   // 1/sqrt(64)
    const size_t rstride = 3 * D_MOD;
    const float* qbase = g_qkv + (size_t)b * S_LEN * rstride + h * HD;

    // Load Q tile, transposed + scaled
    {
        const int c4 = tid & 15;
        const int i0 = tid >> 4;
        #pragma unroll
        for (int it = 0; it < 4; it++) {
            int i = i0 + it * 16;
            float4 v = *(const float4*)(qbase + (size_t)(q0 + i) * rstride + 4 * c4);
            LDQ(4 * c4 + 0, i) = v.x * scale;
            LDQ(4 * c4 + 1, i) = v.y * scale;
            LDQ(4 * c4 + 2, i) = v.z * scale;
            LDQ(4 * c4 + 3, i) = v.w * scale;
        }
    }

    float m[4], l[4], o[4][4];
    #pragma unroll
    for (int r = 0; r < 4; r++) {
        m[r] = -1e30f;
        l[r] = 0.0f;
        #pragma unroll
        for (int c = 0; c < 4; c++) o[r][c] = 0.0f;
    }

    for (int kt = 0; kt < S_LEN / 64; kt++) {
        __syncthreads();   // protect sK/sV/sP from previous iteration's readers
        // Load K,V tiles (coalesced float4 reads, scalar smem stores)
        {
            const int c4 = tid & 15;
            const int j0 = tid >> 4;
            #pragma unroll
            for (int it = 0; it < 4; it++) {
                int j = j0 + it * 16;
                const float* kb = qbase + (size_t)(kt * 64 + j) * rstride + 4 * c4;
                float4 kv = *(const float4*)(kb + D_MOD);
                float4 vv = *(const float4*)(kb + 2 * D_MOD);
                LDK(j, 4 * c4 + 0) = kv.x;
                LDK(j, 4 * c4 + 1) = kv.y;
                LDK(j, 4 * c4 + 2) = kv.z;
                LDK(j, 4 * c4 + 3) = kv.w;
                LDV(j, 4 * c4 + 0) = vv.x;
                LDV(j, 4 * c4 + 1) = vv.y;
                LDV(j, 4 * c4 + 2) = vv.z;
                LDV(j, 4 * c4 + 3) = vv.w;
            }
        }
        __syncthreads();

        // S = Q K^T  (4x4 per thread)
        float s[4][4];
        #pragma unroll
        for (int r = 0; r < 4; r++)
            #pragma unroll
            for (int c = 0; c < 4; c++) s[r][c] = 0.0f;

        #pragma unroll 8
        for (int d = 0; d < 64; d++) {
            float qv[4], kv[4];
            #pragma unroll
            for (int r = 0; r < 4; r++) qv[r] = LDQ(d, 4 * ty + r);
            #pragma unroll
            for (int c = 0; c < 4; c++) kv[c] = LDK(4 * tx + c, d);
            #pragma unroll
            for (int r = 0; r < 4; r++)
                #pragma unroll
                for (int c = 0; c < 4; c++)
                    s[r][c] = fmaf(qv[r], kv[c], s[r][c]);
        }

        // Online softmax (row stats replicated across the 16 tx lanes)
        float mloc[4], rs[4], fac[4];
        #pragma unroll
        for (int r = 0; r < 4; r++) {
            mloc[r] = fmaxf(fmaxf(s[r][0], s[r][1]), fmaxf(s[r][2], s[r][3]));
        }
        #pragma unroll
        for (int off = 8; off > 0; off >>= 1)
            #pragma unroll
            for (int r = 0; r < 4; r++)
                mloc[r] = fmaxf(mloc[r], __shfl_xor_sync(0xffffffffu, mloc[r], off));
        #pragma unroll
        for (int r = 0; r < 4; r++) {
            float mn = fmaxf(m[r], mloc[r]);
            fac[r] = __expf(m[r] - mn);
            m[r] = mn;
            float sum = 0.0f;
            #pragma unroll
            for (int c = 0; c < 4; c++) {
                s[r][c] = __expf(s[r][c] - mn);
                sum += s[r][c];
            }
            rs[r] = sum;
        }
        #pragma unroll
        for (int off = 8; off > 0; off >>= 1)
            #pragma unroll
            for (int r = 0; r < 4; r++)
                rs[r] += __shfl_xor_sync(0xffffffffu, rs[r], off);
        #pragma unroll
        for (int r = 0; r < 4; r++) {
            l[r] = l[r] * fac[r] + rs[r];
            #pragma unroll
            for (int c = 0; c < 4; c++) o[r][c] *= fac[r];
        }

        // Publish P
        #pragma unroll
        for (int r = 0; r < 4; r++)
            #pragma unroll
            for (int c = 0; c < 4; c++)
                LDP(4 * ty + r, 4 * tx + c) = s[r][c];
        __syncthreads();

        // O += P V
        #pragma unroll 8
        for (int j = 0; j < 64; j++) {
            float pr[4], vc[4];
            #pragma unroll
            for (int r = 0; r < 4; r++) pr[r] = LDP(4 * ty + r, j);
            #pragma unroll
            for (int c = 0; c < 4; c++) vc[c] = LDV(j, 4 * tx + c);
            #pragma unroll
            for (int r = 0; r < 4; r++)
                #pragma unroll
                for (int c = 0; c < 4; c++)
                    o[r][c] = fmaf(pr[r], vc[c], o[r][c]);
        }
    }

    // Epilogue: normalize + write to [B*S, D] layout
    float* obase = g_att + (size_t)b * S_LEN * D_MOD + h * HD;
    #pragma unroll
    for (int r = 0; r < 4; r++) {
        float inv = 1.0f / l[r];
        float4 v = make_float4(o[r][0] * inv, o[r][1] * inv,
                               o[r][2] * inv, o[r][3] * inv);
        *(float4*)(obase + (size_t)(q0 + 4 * ty + r) * D_MOD + 4 * tx) = v;
    }
}

// ---------------------------------------------------------------------------
extern "C" void kernel_launch(void* const* d_in, const int* in_sizes, int n_in,
                              void* d_out, int out_size)
{
    // Identify inputs by element count (robust to ordering)
    const float* x = nullptr;      // 4*2048*1024  = 8388608
    const float* w_qkv = nullptr;  // 1024*3072    = 3145728
    const float* w_out = nullptr;  // 1024*1024    = 1048576
    for (int i = 0; i < n_in; i++) {
        if (in_sizes[i] == B_SZ * S_LEN * D_MOD) x = (const float*)d_in[i];
        else if (in_sizes[i] == D_MOD * 3 * D_MOD) w_qkv = (const float*)d_in[i];
        else if (in_sizes[i] == D_MOD * D_MOD) w_out = (const float*)d_in[i];
    }
    float* out = (float*)d_out;

    float* qkv_p = nullptr;
    float* att_p = nullptr;
    cudaGetSymbolAddress((void**)&qkv_p, g_qkv);
    cudaGetSymbolAddress((void**)&att_p, g_att);

    const int attn_smem_bytes = 4 * 64 * 65 * (int)sizeof(float);  // 66560
    cudaFuncSetAttribute(attn_kernel, cudaFuncAttributeMaxDynamicSharedMemorySize,
                         attn_smem_bytes);

    dim3 blk(256);

    // 1) QKV projection: [8192,1024] x [1024,3072]
    sgemm_kernel<<<dim3(3 * D_MOD / 128, B_SZ * S_LEN / 128), blk>>>(
        x, w_qkv, qkv_p, B_SZ * S_LEN, 3 * D_MOD, D_MOD);

    // 2) Attention per (b,h,q-tile)
    attn_kernel<<<dim3(S_LEN / 64, B_SZ * H_CNT), blk, attn_smem_bytes>>>();

    // 3) Output projection: [8192,1024] x [1024,1024]
    sgemm_kernel<<<dim3(D_MOD / 128, B_SZ * S_LEN / 128), blk>>>(
        att_p, w_out, out, B_SZ * S_LEN, D_MOD, D_MOD);
}

// round 5
// speedup vs baseline: 1.2414x; 1.2414x over previous
#include <cuda_runtime.h>
#include <cstdint>

#define B_SZ 4
#define S_LEN 2048
#define D_MOD 1024
#define H_CNT 16
#define HD 64

// Scratch (allocation-free rule: __device__ globals)
__device__ float g_qkv[(size_t)B_SZ * S_LEN * 3 * D_MOD];   // [B*S, 3D]
__device__ float g_att[(size_t)B_SZ * S_LEN * D_MOD];       // [B*S, D]

// ---------------------------------------------------------------------------
// tf32 helpers: split x = hi + lo, both exactly representable as tf32.
// ---------------------------------------------------------------------------
__device__ __forceinline__ uint32_t f2tf32(float x) {
    uint32_t r;
    asm("cvt.rna.tf32.f32 %0, %1;" : "=r"(r) : "f"(x));
    return r;
}
__device__ __forceinline__ void split2(float x, float& hi, float& lo) {
    uint32_t h = f2tf32(x);
    hi = __uint_as_float(h);
    lo = __uint_as_float(f2tf32(x - hi));
}
// D += A(16x8) * B(8x8), tf32 operands already converted, fp32 accum.
__device__ __forceinline__ void mma8(float* c, const float* a, const float* b) {
    asm volatile(
        "mma.sync.aligned.m16n8k8.row.col.f32.tf32.tf32.f32 "
        "{%0,%1,%2,%3}, {%4,%5,%6,%7}, {%8,%9}, {%0,%1,%2,%3};"
        : "+f"(c[0]), "+f"(c[1]), "+f"(c[2]), "+f"(c[3])
        : "r"(__float_as_uint(a[0])), "r"(__float_as_uint(a[1])),
          "r"(__float_as_uint(a[2])), "r"(__float_as_uint(a[3])),
          "r"(__float_as_uint(b[0])), "r"(__float_as_uint(b[1])));
}

// ---------------------------------------------------------------------------
// GEMM: C[M,N] = A[M,K]*B[K,N], split-tf32 mma. 128x128x16 tile, 256 threads,
// 8 warps as 2(M)x4(N); warp tile 64x32 = 4x4 m16n8 tiles.
// ---------------------------------------------------------------------------
#define BM 128
#define BN 128
#define BK 16
#define ASTR (BM + 4)
#define BSTR (BN + 4)

__global__ __launch_bounds__(256) void gemm_tf32(
    const float* __restrict__ A, const float* __restrict__ B,
    float* __restrict__ C, int M, int N, int K)
{
    __shared__ float sAhi[BK][ASTR], sAlo[BK][ASTR];   // [k][m]
    __shared__ float sBhi[BK][BSTR], sBlo[BK][BSTR];   // [k][n]

    const int tid = threadIdx.x;
    const int lane = tid & 31, warp = tid >> 5;
    const int wm = warp & 1, wn = warp >> 1;
    const int g = lane >> 2, t = lane & 3;
    const int m0 = blockIdx.y * BM, n0 = blockIdx.x * BN;

    const int ar = tid >> 2;            // 0..63
    const int ac = (tid & 3) * 4;       // 0,4,8,12
    const int br = tid >> 5;            // 0..7
    const int bc = (tid & 31) * 4;      // 0..124

    float acc[4][4][4];
    #pragma unroll
    for (int i = 0; i < 4; i++)
        #pragma unroll
        for (int j = 0; j < 4; j++)
            #pragma unroll
            for (int e = 0; e < 4; e++) acc[i][j][e] = 0.0f;

    for (int k0 = 0; k0 < K; k0 += BK) {
        // ---- load + split tiles ----
        #pragma unroll
        for (int p = 0; p < 2; p++) {
            int row = ar + 64 * p;
            float4 v = *(const float4*)(A + (size_t)(m0 + row) * K + k0 + ac);
            float hi, lo;
            split2(v.x, hi, lo); sAhi[ac + 0][row] = hi; sAlo[ac + 0][row] = lo;
            split2(v.y, hi, lo); sAhi[ac + 1][row] = hi; sAlo[ac + 1][row] = lo;
            split2(v.z, hi, lo); sAhi[ac + 2][row] = hi; sAlo[ac + 2][row] = lo;
            split2(v.w, hi, lo); sAhi[ac + 3][row] = hi; sAlo[ac + 3][row] = lo;
        }
        #pragma unroll
        for (int p = 0; p < 2; p++) {
            int row = br + 8 * p;
            float4 v = *(const float4*)(B + (size_t)(k0 + row) * N + n0 + bc);
            float hi, lo;
            split2(v.x, hi, lo); sBhi[row][bc + 0] = hi; sBlo[row][bc + 0] = lo;
            split2(v.y, hi, lo); sBhi[row][bc + 1] = hi; sBlo[row][bc + 1] = lo;
            split2(v.z, hi, lo); sBhi[row][bc + 2] = hi; sBlo[row][bc + 2] = lo;
            split2(v.w, hi, lo); sBhi[row][bc + 3] = hi; sBlo[row][bc + 3] = lo;
        }
        __syncthreads();

        // ---- compute: 2 k-steps of 8 ----
        #pragma unroll
        for (int ks = 0; ks < 2; ks++) {
            const int kb = ks * 8;
            float ahi[4][4], alo[4][4], bhi[4][2], blo[4][2];
            #pragma unroll
            for (int mt = 0; mt < 4; mt++) {
                int mb = wm * 64 + mt * 16;
                ahi[mt][0] = sAhi[kb + t][mb + g];       alo[mt][0] = sAlo[kb + t][mb + g];
                ahi[mt][1] = sAhi[kb + t][mb + g + 8];   alo[mt][1] = sAlo[kb + t][mb + g + 8];
                ahi[mt][2] = sAhi[kb + t + 4][mb + g];     alo[mt][2] = sAlo[kb + t + 4][mb + g];
                ahi[mt][3] = sAhi[kb + t + 4][mb + g + 8]; alo[mt][3] = sAlo[kb + t + 4][mb + g + 8];
            }
            #pragma unroll
            for (int nt = 0; nt < 4; nt++) {
                int nb = wn * 32 + nt * 8;
                bhi[nt][0] = sBhi[kb + t][nb + g];     blo[nt][0] = sBlo[kb + t][nb + g];
                bhi[nt][1] = sBhi[kb + t + 4][nb + g]; blo[nt][1] = sBlo[kb + t + 4][nb + g];
            }
            #pragma unroll
            for (int mt = 0; mt < 4; mt++)
                #pragma unroll
                for (int nt = 0; nt < 4; nt++) {
                    mma8(acc[mt][nt], ahi[mt], bhi[nt]);
                    mma8(acc[mt][nt], ahi[mt], blo[nt]);
                    mma8(acc[mt][nt], alo[mt], bhi[nt]);
                }
        }
        __syncthreads();
    }

    // ---- epilogue ----
    #pragma unroll
    for (int mt = 0; mt < 4; mt++) {
        int row = m0 + wm * 64 + mt * 16 + g;
        #pragma unroll
        for (int nt = 0; nt < 4; nt++) {
            int col = n0 + wn * 32 + nt * 8 + 2 * t;
            *(float2*)(C + (size_t)row * N + col) =
                make_float2(acc[mt][nt][0], acc[mt][nt][1]);
            *(float2*)(C + (size_t)(row + 8) * N + col) =
                make_float2(acc[mt][nt][2], acc[mt][nt][3]);
        }
    }
}

// ---------------------------------------------------------------------------
// Flash attention, split-tf32 mma. Block = (b, h, 128-query tile).
// 8 warps, each owns 16 query rows for the whole block.
// smem: sK (hi/lo) [key][d] stride 68, sVt (hi/lo) [d][key] stride 67,
//       sP (hi/lo) [q][key] stride 68 (warp-private rows; also Q staging).
// ---------------------------------------------------------------------------
#define KSTR 68
#define VSTR 67
#define PSTR 68

__global__ __launch_bounds__(256) void attn_tf32()
{
    extern __shared__ float sm[];
    float* sKhi = sm;                     // 64*68
    float* sKlo = sKhi + 64 * KSTR;
    float* sVhi = sKlo + 64 * KSTR;       // 64*67, [d][key]
    float* sVlo = sVhi + 64 * VSTR;
    float* sPhi = sVlo + 64 * VSTR;       // 128*68 (also Q staging)
    float* sPlo = sPhi + 128 * PSTR;

    const int tid = threadIdx.x;
    const int lane = tid & 31, warp = tid >> 5;
    const int g = lane >> 2, t = lane & 3;
    const int b = blockIdx.y >> 4, h = blockIdx.y & 15;
    const int q0 = blockIdx.x * 128;
    const size_t rstr = 3 * D_MOD;
    const float* base = g_qkv + (size_t)b * S_LEN * rstr + h * HD;

    // ---- stage Q (pre-scaled) into sPhi ----
    {
        const int c4 = tid & 15, r0 = tid >> 4;
        #pragma unroll
        for (int p = 0; p < 8; p++) {
            int r = r0 + p * 16;
            float4 v = *(const float4*)(base + (size_t)(q0 + r) * rstr + 4 * c4);
            sPhi[r * PSTR + 4 * c4 + 0] = v.x * 0.125f;
            sPhi[r * PSTR + 4 * c4 + 1] = v.y * 0.125f;
            sPhi[r * PSTR + 4 * c4 + 2] = v.z * 0.125f;
            sPhi[r * PSTR + 4 * c4 + 3] = v.w * 0.125f;
        }
    }
    __syncthreads();

    // ---- Q fragments in registers (split once, reused for all K tiles) ----
    const int mq = warp * 16;
    float qhi[8][4], qlo[8][4];
    #pragma unroll
    for (int ds = 0; ds < 8; ds++) {
        int kb = ds * 8;
        split2(sPhi[(mq + g) * PSTR + kb + t],         qhi[ds][0], qlo[ds][0]);
        split2(sPhi[(mq + g + 8) * PSTR + kb + t],     qhi[ds][1], qlo[ds][1]);
        split2(sPhi[(mq + g) * PSTR + kb + t + 4],     qhi[ds][2], qlo[ds][2]);
        split2(sPhi[(mq + g + 8) * PSTR + kb + t + 4], qhi[ds][3], qlo[ds][3]);
    }

    float o[8][4];
    #pragma unroll
    for (int i = 0; i < 8; i++)
        #pragma unroll
        for (int e = 0; e < 4; e++) o[i][e] = 0.0f;
    float m0r = -1e30f, m1r = -1e30f, l0 = 0.0f, l1 = 0.0f;

    for (int kt = 0; kt < S_LEN / 64; kt++) {
        __syncthreads();   // previous iteration's sK/sV readers done
        // ---- load + split K,V tiles (V stored transposed) ----
        {
            const int c4 = tid & 15, j0 = tid >> 4;
            #pragma unroll
            for (int p = 0; p < 4; p++) {
                int j = j0 + p * 16;
                const float* kb_ = base + (size_t)(kt * 64 + j) * rstr + 4 * c4;
                float4 kv = *(const float4*)(kb_ + D_MOD);
                float4 vv = *(const float4*)(kb_ + 2 * D_MOD);
                float hi, lo;
                split2(kv.x, hi, lo); sKhi[j * KSTR + 4 * c4 + 0] = hi; sKlo[j * KSTR + 4 * c4 + 0] = lo;
                split2(kv.y, hi, lo); sKhi[j * KSTR + 4 * c4 + 1] = hi; sKlo[j * KSTR + 4 * c4 + 1] = lo;
                split2(kv.z, hi, lo); sKhi[j * KSTR + 4 * c4 + 2] = hi; sKlo[j * KSTR + 4 * c4 + 2] = lo;
                split2(kv.w, hi, lo); sKhi[j * KSTR + 4 * c4 + 3] = hi; sKlo[j * KSTR + 4 * c4 + 3] = lo;
                split2(vv.x, hi, lo); sVhi[(4 * c4 + 0) * VSTR + j] = hi; sVlo[(4 * c4 + 0) * VSTR + j] = lo;
                split2(vv.y, hi, lo); sVhi[(4 * c4 + 1) * VSTR + j] = hi; sVlo[(4 * c4 + 1) * VSTR + j] = lo;
                split2(vv.z, hi, lo); sVhi[(4 * c4 + 2) * VSTR + j] = hi; sVlo[(4 * c4 + 2) * VSTR + j] = lo;
                split2(vv.w, hi, lo); sVhi[(4 * c4 + 3) * VSTR + j] = hi; sVlo[(4 * c4 + 3) * VSTR + j] = lo;
            }
        }
        __syncthreads();

        // ---- S = Q K^T (16 q-rows x 64 keys per warp) ----
        float s[8][4];
        #pragma unroll
        for (int i = 0; i < 8; i++)
            #pragma unroll
            for (int e = 0; e < 4; e++) s[i][e] = 0.0f;

        #pragma unroll
        for (int ds = 0; ds < 8; ds++) {
            int kb = ds * 8;
            #pragma unroll
            for (int nt = 0; nt < 8; nt++) {
                int nb = nt * 8;
                float bhi[2], blo[2];
                bhi[0] = sKhi[(nb + g) * KSTR + kb + t];     blo[0] = sKlo[(nb + g) * KSTR + kb + t];
                bhi[1] = sKhi[(nb + g) * KSTR + kb + t + 4]; blo[1] = sKlo[(nb + g) * KSTR + kb + t + 4];
                mma8(s[nt], qhi[ds], bhi);
                mma8(s[nt], qhi[ds], blo);
                mma8(s[nt], qlo[ds], bhi);
            }
        }

        // ---- online softmax on C fragments (rows g, g+8) ----
        float mx0 = -1e30f, mx1 = -1e30f;
        #pragma unroll
        for (int nt = 0; nt < 8; nt++) {
            mx0 = fmaxf(mx0, fmaxf(s[nt][0], s[nt][1]));
            mx1 = fmaxf(mx1, fmaxf(s[nt][2], s[nt][3]));
        }
        mx0 = fmaxf(mx0, __shfl_xor_sync(0xffffffffu, mx0, 1));
        mx0 = fmaxf(mx0, __shfl_xor_sync(0xffffffffu, mx0, 2));
        mx1 = fmaxf(mx1, __shfl_xor_sync(0xffffffffu, mx1, 1));
        mx1 = fmaxf(mx1, __shfl_xor_sync(0xffffffffu, mx1, 2));

        float mn0 = fmaxf(m0r, mx0), mn1 = fmaxf(m1r, mx1);
        float f0 = __expf(m0r - mn0), f1 = __expf(m1r - mn1);
        m0r = mn0; m1r = mn1;

        float rs0 = 0.0f, rs1 = 0.0f;
        #pragma unroll
        for (int nt = 0; nt < 8; nt++) {
            s[nt][0] = __expf(s[nt][0] - mn0); rs0 += s[nt][0];
            s[nt][1] = __expf(s[nt][1] - mn0); rs0 += s[nt][1];
            s[nt][2] = __expf(s[nt][2] - mn1); rs1 += s[nt][2];
            s[nt][3] = __expf(s[nt][3] - mn1); rs1 += s[nt][3];
        }
        rs0 += __shfl_xor_sync(0xffffffffu, rs0, 1);
        rs0 += __shfl_xor_sync(0xffffffffu, rs0, 2);
        rs1 += __shfl_xor_sync(0xffffffffu, rs1, 1);
        rs1 += __shfl_xor_sync(0xffffffffu, rs1, 2);
        l0 = l0 * f0 + rs0;
        l1 = l1 * f1 + rs1;
        #pragma unroll
        for (int nt = 0; nt < 8; nt++) {
            o[nt][0] *= f0; o[nt][1] *= f0;
            o[nt][2] *= f1; o[nt][3] *= f1;
        }

        // ---- store split P (warp-private rows: no barrier needed) ----
        #pragma unroll
        for (int nt = 0; nt < 8; nt++) {
            int col = nt * 8 + 2 * t;
            float hi, lo;
            split2(s[nt][0], hi, lo); sPhi[(mq + g) * PSTR + col] = hi;     sPlo[(mq + g) * PSTR + col] = lo;
            split2(s[nt][1], hi, lo); sPhi[(mq + g) * PSTR + col + 1] = hi; sPlo[(mq + g) * PSTR + col + 1] = lo;
            split2(s[nt][2], hi, lo); sPhi[(mq + g + 8) * PSTR + col] = hi;     sPlo[(mq + g + 8) * PSTR + col] = lo;
            split2(s[nt][3], hi, lo); sPhi[(mq + g + 8) * PSTR + col + 1] = hi; sPlo[(mq + g + 8) * PSTR + col + 1] = lo;
        }

        // ---- O += P V ----
        #pragma unroll
        for (int ks = 0; ks < 8; ks++) {
            int kb = ks * 8;
            float ahi[4], alo[4];
            ahi[0] = sPhi[(mq + g) * PSTR + kb + t];         alo[0] = sPlo[(mq + g) * PSTR + kb + t];
            ahi[1] = sPhi[(mq + g + 8) * PSTR + kb + t];     alo[1] = sPlo[(mq + g + 8) * PSTR + kb + t];
            ahi[2] = sPhi[(mq + g) * PSTR + kb + t + 4];     alo[2] = sPlo[(mq + g) * PSTR + kb + t + 4];
            ahi[3] = sPhi[(mq + g + 8) * PSTR + kb + t + 4]; alo[3] = sPlo[(mq + g + 8) * PSTR + kb + t + 4];
            #pragma unroll
            for (int nt = 0; nt < 8; nt++) {
                int nb = nt * 8;
                float bhi[2], blo[2];
                bhi[0] = sVhi[(nb + g) * VSTR + kb + t];     blo[0] = sVlo[(nb + g) * VSTR + kb + t];
                bhi[1] = sVhi[(nb + g) * VSTR + kb + t + 4]; blo[1] = sVlo[(nb + g) * VSTR + kb + t + 4];
                mma8(o[nt], ahi, bhi);
                mma8(o[nt], ahi, blo);
                mma8(o[nt], alo, bhi);
            }
        }
    }

    // ---- epilogue: normalize, write [B*S, D] ----
    float inv0 = 1.0f / l0, inv1 = 1.0f / l1;
    float* ob = g_att + ((size_t)b * S_LEN + q0 + mq) * D_MOD + h * HD;
    #pragma unroll
    for (int nt = 0; nt < 8; nt++) {
        int col = nt * 8 + 2 * t;
        *(float2*)(ob + (size_t)g * D_MOD + col) =
            make_float2(o[nt][0] * inv0, o[nt][1] * inv0);
        *(float2*)(ob + (size_t)(g + 8) * D_MOD + col) =
            make_float2(o[nt][2] * inv1, o[nt][3] * inv1);
    }
}

// ---------------------------------------------------------------------------
extern "C" void kernel_launch(void* const* d_in, const int* in_sizes, int n_in,
                              void* d_out, int out_size)
{
    const float* x = nullptr;
    const float* w_qkv = nullptr;
    const float* w_out = nullptr;
    for (int i = 0; i < n_in; i++) {
        if (in_sizes[i] == B_SZ * S_LEN * D_MOD) x = (const float*)d_in[i];
        else if (in_sizes[i] == D_MOD * 3 * D_MOD) w_qkv = (const float*)d_in[i];
        else if (in_sizes[i] == D_MOD * D_MOD) w_out = (const float*)d_in[i];
    }
    float* out = (float*)d_out;

    float* qkv_p = nullptr;
    float* att_p = nullptr;
    cudaGetSymbolAddress((void**)&qkv_p, g_qkv);
    cudaGetSymbolAddress((void**)&att_p, g_att);

    const int attn_smem = (2 * 64 * KSTR + 2 * 64 * VSTR + 2 * 128 * PSTR) * (int)sizeof(float);
    cudaFuncSetAttribute(attn_tf32, cudaFuncAttributeMaxDynamicSharedMemorySize, attn_smem);

    dim3 blk(256);

    // 1) QKV projection: [8192,1024] x [1024,3072]
    gemm_tf32<<<dim3(3 * D_MOD / BN, B_SZ * S_LEN / BM), blk>>>(
        x, w_qkv, qkv_p, B_SZ * S_LEN, 3 * D_MOD, D_MOD);

    // 2) Attention: (b,h) x 128-query tiles
    attn_tf32<<<dim3(S_LEN / 128, B_SZ * H_CNT), blk, attn_smem>>>();

    // 3) Output projection: [8192,1024] x [1024,1024]
    gemm_tf32<<<dim3(D_MOD / BN, B_SZ * S_LEN / BM), blk>>>(
        att_p, w_out, out, B_SZ * S_LEN, D_MOD, D_MOD);
}

// round 7
// speedup vs baseline: 2.0443x; 1.6468x over previous
#include <cuda_runtime.h>
#include <cstdint>

#define B_SZ 4
#define S_LEN 2048
#define D_MOD 1024
#define H_CNT 16
#define HD 64

// Scratch (allocation-free rule: __device__ globals)
__device__ float g_qkv[(size_t)B_SZ * S_LEN * 3 * D_MOD];   // [B*S, 3D]
__device__ float g_att[(size_t)B_SZ * S_LEN * D_MOD];       // [B*S, D]

// ---------------------------------------------------------------------------
// tf32 helpers
// ---------------------------------------------------------------------------
__device__ __forceinline__ uint32_t f2tf32(float x) {
    uint32_t r;
    asm("cvt.rna.tf32.f32 %0, %1;" : "=r"(r) : "f"(x));
    return r;
}
__device__ __forceinline__ float2 splitf2(float x) {
    float hi = __uint_as_float(f2tf32(x));
    float lo = __uint_as_float(f2tf32(x - hi));
    return make_float2(hi, lo);
}
// D += A(16x8) * B(8x8), tf32, fp32 accum
__device__ __forceinline__ void mma8(float* c, const float* a, const float* b) {
    asm volatile(
        "mma.sync.aligned.m16n8k8.row.col.f32.tf32.tf32.f32 "
        "{%0,%1,%2,%3}, {%4,%5,%6,%7}, {%8,%9}, {%0,%1,%2,%3};"
        : "+f"(c[0]), "+f"(c[1]), "+f"(c[2]), "+f"(c[3])
        : "r"(__float_as_uint(a[0])), "r"(__float_as_uint(a[1])),
          "r"(__float_as_uint(a[2])), "r"(__float_as_uint(a[3])),
          "r"(__float_as_uint(b[0])), "r"(__float_as_uint(b[1])));
}

// ---------------------------------------------------------------------------
// GEMM: C = A*B, split-tf32. 128x128x16 tile, 256 thr, 8 warps 2(M)x4(N).
// smem packed float2 (hi,lo): sA [m][k] stride 18 (k=16+pad),
//                             sB [k][n] stride 132 (n=128+pad).
// ---------------------------------------------------------------------------
#define BM 128
#define BN 128
#define BK 16
#define AS2 18
#define BS2 132

__global__ __launch_bounds__(256, 2) void gemm_tf32(
    const float* __restrict__ A, const float* __restrict__ B,
    float* __restrict__ C, int M, int N, int K)
{
    __shared__ float2 sA[BM][AS2];
    __shared__ float2 sB[BK][BS2];

    const int tid = threadIdx.x;
    const int lane = tid & 31, warp = tid >> 5;
    const int wm = warp & 1, wn = warp >> 1;
    const int g = lane >> 2, t = lane & 3;
    const int m0 = blockIdx.y * BM, n0 = blockIdx.x * BN;

    const int ar = tid >> 2;            // 0..63
    const int ac = (tid & 3) * 4;       // 0,4,8,12
    const int br = tid >> 5;            // 0..7
    const int bc = (tid & 31) * 4;      // 0..124

    float acc[4][4][4];
    #pragma unroll
    for (int i = 0; i < 4; i++)
        #pragma unroll
        for (int j = 0; j < 4; j++)
            #pragma unroll
            for (int e = 0; e < 4; e++) acc[i][j][e] = 0.0f;

    for (int k0 = 0; k0 < K; k0 += BK) {
        #pragma unroll
        for (int p = 0; p < 2; p++) {
            int row = ar + 64 * p;
            float4 v = *(const float4*)(A + (size_t)(m0 + row) * K + k0 + ac);
            float2 e0 = splitf2(v.x), e1 = splitf2(v.y);
            float2 e2 = splitf2(v.z), e3 = splitf2(v.w);
            *(float4*)&sA[row][ac]     = make_float4(e0.x, e0.y, e1.x, e1.y);
            *(float4*)&sA[row][ac + 2] = make_float4(e2.x, e2.y, e3.x, e3.y);
        }
        #pragma unroll
        for (int p = 0; p < 2; p++) {
            int row = br + 8 * p;
            float4 v = *(const float4*)(B + (size_t)(k0 + row) * N + n0 + bc);
            float2 e0 = splitf2(v.x), e1 = splitf2(v.y);
            float2 e2 = splitf2(v.z), e3 = splitf2(v.w);
            *(float4*)&sB[row][bc]     = make_float4(e0.x, e0.y, e1.x, e1.y);
            *(float4*)&sB[row][bc + 2] = make_float4(e2.x, e2.y, e3.x, e3.y);
        }
        __syncthreads();

        #pragma unroll
        for (int ks = 0; ks < 2; ks++) {
            const int kb = ks * 8;
            float2 af[4][4], bf[4][2];
            #pragma unroll
            for (int mt = 0; mt < 4; mt++) {
                int mb = wm * 64 + mt * 16;
                af[mt][0] = sA[mb + g][kb + t];
                af[mt][1] = sA[mb + g + 8][kb + t];
                af[mt][2] = sA[mb + g][kb + t + 4];
                af[mt][3] = sA[mb + g + 8][kb + t + 4];
            }
            #pragma unroll
            for (int nt = 0; nt < 4; nt++) {
                int nb = wn * 32 + nt * 8;
                bf[nt][0] = sB[kb + t][nb + g];
                bf[nt][1] = sB[kb + t + 4][nb + g];
            }
            #pragma unroll
            for (int mt = 0; mt < 4; mt++) {
                float ahi[4] = {af[mt][0].x, af[mt][1].x, af[mt][2].x, af[mt][3].x};
                float alo[4] = {af[mt][0].y, af[mt][1].y, af[mt][2].y, af[mt][3].y};
                #pragma unroll
                for (int nt = 0; nt < 4; nt++) {
                    float bhi[2] = {bf[nt][0].x, bf[nt][1].x};
                    float blo[2] = {bf[nt][0].y, bf[nt][1].y};
                    mma8(acc[mt][nt], ahi, bhi);
                    mma8(acc[mt][nt], ahi, blo);
                    mma8(acc[mt][nt], alo, bhi);
                }
            }
        }
        __syncthreads();
    }

    #pragma unroll
    for (int mt = 0; mt < 4; mt++) {
        int row = m0 + wm * 64 + mt * 16 + g;
        #pragma unroll
        for (int nt = 0; nt < 4; nt++) {
            int col = n0 + wn * 32 + nt * 8 + 2 * t;
            *(float2*)(C + (size_t)row * N + col) =
                make_float2(acc[mt][nt][0], acc[mt][nt][1]);
            *(float2*)(C + (size_t)(row + 8) * N + col) =
                make_float2(acc[mt][nt][2], acc[mt][nt][3]);
        }
    }
}

// ---------------------------------------------------------------------------
// Flash attention, split-tf32. Block = (b, h, 256-query tile), 512 threads,
// 16 warps x 16 q rows. K/V tiles: 64 keys.
// smem packed float2, row stride QS2=68 (64 values + pad):
//   sQ [q][d] 256x68, sK [key][d] 64x68, sV [key][d] 64x68.
// P never touches smem: S C-frag -> A-frag via shfl.
// ---------------------------------------------------------------------------
#define QS2 68

__global__ __launch_bounds__(512, 1) void attn_tf32()
{
    extern __shared__ float2 smf2[];
    float2* sQ = smf2;                  // 256*68
    float2* sK = sQ + 256 * QS2;        // 64*68
    float2* sV = sK + 64 * QS2;         // 64*68

    const int tid = threadIdx.x;
    const int lane = tid & 31, warp = tid >> 5;
    const int g = lane >> 2, t = lane & 3;
    const int b = blockIdx.y >> 4, h = blockIdx.y & 15;
    const int q0 = blockIdx.x * 256;
    const int mq = warp * 16;
    const size_t rstr = 3 * D_MOD;
    const float* base = g_qkv + (size_t)b * S_LEN * rstr + h * HD;

    // ---- stage Q: load, scale, split, store packed ----
    {
        const int c4 = tid & 15, r0 = tid >> 4;   // c4: 16 float4 cols, r0: 0..31
        #pragma unroll
        for (int p = 0; p < 8; p++) {
            int r = r0 + p * 32;
            float4 v = *(const float4*)(base + (size_t)(q0 + r) * rstr + 4 * c4);
            float2 e0 = splitf2(v.x * 0.125f), e1 = splitf2(v.y * 0.125f);
            float2 e2 = splitf2(v.z * 0.125f), e3 = splitf2(v.w * 0.125f);
            *(float4*)&sQ[r * QS2 + 4 * c4]     = make_float4(e0.x, e0.y, e1.x, e1.y);
            *(float4*)&sQ[r * QS2 + 4 * c4 + 2] = make_float4(e2.x, e2.y, e3.x, e3.y);
        }
    }

    float o[8][4];
    #pragma unroll
    for (int i = 0; i < 8; i++)
        #pragma unroll
        for (int e = 0; e < 4; e++) o[i][e] = 0.0f;
    float m0r = -1e30f, m1r = -1e30f, l0 = 0.0f, l1 = 0.0f;

    // shuffle constants for C-frag -> A-frag (P) conversion
    const int ls1 = (lane & ~3) + (t >> 1);
    const int ls2 = ls1 + 2;
    const bool odd = (t & 1);

    for (int kt = 0; kt < S_LEN / 64; kt++) {
        __syncthreads();   // covers sQ staging (iter 0) and prior sK/sV readers
        // ---- load + split K,V (natural [key][d]) ----
        {
            const int c4 = tid & 15, j0 = tid >> 4;   // j0: 0..31
            #pragma unroll
            for (int p = 0; p < 2; p++) {
                int j = j0 + p * 32;
                const float* kb_ = base + (size_t)(kt * 64 + j) * rstr + 4 * c4;
                float4 kv = *(const float4*)(kb_ + D_MOD);
                float4 vv = *(const float4*)(kb_ + 2 * D_MOD);
                float2 e0 = splitf2(kv.x), e1 = splitf2(kv.y);
                float2 e2 = splitf2(kv.z), e3 = splitf2(kv.w);
                *(float4*)&sK[j * QS2 + 4 * c4]     = make_float4(e0.x, e0.y, e1.x, e1.y);
                *(float4*)&sK[j * QS2 + 4 * c4 + 2] = make_float4(e2.x, e2.y, e3.x, e3.y);
                e0 = splitf2(vv.x); e1 = splitf2(vv.y);
                e2 = splitf2(vv.z); e3 = splitf2(vv.w);
                *(float4*)&sV[j * QS2 + 4 * c4]     = make_float4(e0.x, e0.y, e1.x, e1.y);
                *(float4*)&sV[j * QS2 + 4 * c4 + 2] = make_float4(e2.x, e2.y, e3.x, e3.y);
            }
        }
        __syncthreads();

        // ---- S = Q K^T (16 q-rows x 64 keys per warp) ----
        float s[8][4];
        #pragma unroll
        for (int i = 0; i < 8; i++)
            #pragma unroll
            for (int e = 0; e < 4; e++) s[i][e] = 0.0f;

        #pragma unroll
        for (int ds = 0; ds < 8; ds++) {
            int kb = ds * 8;
            float2 q0f = sQ[(mq + g) * QS2 + kb + t];
            float2 q1f = sQ[(mq + g + 8) * QS2 + kb + t];
            float2 q2f = sQ[(mq + g) * QS2 + kb + t + 4];
            float2 q3f = sQ[(mq + g + 8) * QS2 + kb + t + 4];
            float qhi[4] = {q0f.x, q1f.x, q2f.x, q3f.x};
            float qlo[4] = {q0f.y, q1f.y, q2f.y, q3f.y};
            #pragma unroll
            for (int nt = 0; nt < 8; nt++) {
                float2 k0f = sK[(nt * 8 + g) * QS2 + kb + t];
                float2 k1f = sK[(nt * 8 + g) * QS2 + kb + t + 4];
                float bhi[2] = {k0f.x, k1f.x};
                float blo[2] = {k0f.y, k1f.y};
                mma8(s[nt], qhi, bhi);
                mma8(s[nt], qhi, blo);
                mma8(s[nt], qlo, bhi);
            }
        }

        // ---- online softmax (rows g, g+8) ----
        float mx0 = -1e30f, mx1 = -1e30f;
        #pragma unroll
        for (int nt = 0; nt < 8; nt++) {
            mx0 = fmaxf(mx0, fmaxf(s[nt][0], s[nt][1]));
            mx1 = fmaxf(mx1, fmaxf(s[nt][2], s[nt][3]));
        }
        mx0 = fmaxf(mx0, __shfl_xor_sync(0xffffffffu, mx0, 1));
        mx0 = fmaxf(mx0, __shfl_xor_sync(0xffffffffu, mx0, 2));
        mx1 = fmaxf(mx1, __shfl_xor_sync(0xffffffffu, mx1, 1));
        mx1 = fmaxf(mx1, __shfl_xor_sync(0xffffffffu, mx1, 2));

        float mn0 = fmaxf(m0r, mx0), mn1 = fmaxf(m1r, mx1);
        float f0 = __expf(m0r - mn0), f1 = __expf(m1r - mn1);
        m0r = mn0; m1r = mn1;

        float rs0 = 0.0f, rs1 = 0.0f;
        #pragma unroll
        for (int nt = 0; nt < 8; nt++) {
            s[nt][0] = __expf(s[nt][0] - mn0); rs0 += s[nt][0];
            s[nt][1] = __expf(s[nt][1] - mn0); rs0 += s[nt][1];
            s[nt][2] = __expf(s[nt][2] - mn1); rs1 += s[nt][2];
            s[nt][3] = __expf(s[nt][3] - mn1); rs1 += s[nt][3];
        }
        rs0 += __shfl_xor_sync(0xffffffffu, rs0, 1);
        rs0 += __shfl_xor_sync(0xffffffffu, rs0, 2);
        rs1 += __shfl_xor_sync(0xffffffffu, rs1, 1);
        rs1 += __shfl_xor_sync(0xffffffffu, rs1, 2);
        l0 = l0 * f0 + rs0;
        l1 = l1 * f1 + rs1;
        #pragma unroll
        for (int nt = 0; nt < 8; nt++) {
            o[nt][0] *= f0; o[nt][1] *= f0;
            o[nt][2] *= f1; o[nt][3] *= f1;
        }

        // ---- O += P V : P C-frag -> A-frag via shfl, V from smem ----
        #pragma unroll
        for (int ks = 0; ks < 8; ks++) {
            float p00 = __shfl_sync(0xffffffffu, s[ks][0], ls1);
            float p01 = __shfl_sync(0xffffffffu, s[ks][1], ls1);
            float p10 = __shfl_sync(0xffffffffu, s[ks][2], ls1);
            float p11 = __shfl_sync(0xffffffffu, s[ks][3], ls1);
            float p20 = __shfl_sync(0xffffffffu, s[ks][0], ls2);
            float p21 = __shfl_sync(0xffffffffu, s[ks][1], ls2);
            float p30 = __shfl_sync(0xffffffffu, s[ks][2], ls2);
            float p31 = __shfl_sync(0xffffffffu, s[ks][3], ls2);
            float2 A0 = splitf2(odd ? p01 : p00);   // (g,    kb+t)
            float2 A1 = splitf2(odd ? p11 : p10);   // (g+8,  kb+t)
            float2 A2 = splitf2(odd ? p21 : p20);   // (g,    kb+t+4)
            float2 A3 = splitf2(odd ? p31 : p30);   // (g+8,  kb+t+4)
            float ahi[4] = {A0.x, A1.x, A2.x, A3.x};
            float alo[4] = {A0.y, A1.y, A2.y, A3.y};
            int kb = ks * 8;
            #pragma unroll
            for (int nt = 0; nt < 8; nt++) {
                float2 v0f = sV[(kb + t) * QS2 + nt * 8 + g];
                float2 v1f = sV[(kb + t + 4) * QS2 + nt * 8 + g];
                float bhi[2] = {v0f.x, v1f.x};
                float blo[2] = {v0f.y, v1f.y};
                mma8(o[nt], ahi, bhi);
                mma8(o[nt], ahi, blo);
                mma8(o[nt], alo, bhi);
            }
        }
    }

    // ---- epilogue ----
    float inv0 = 1.0f / l0, inv1 = 1.0f / l1;
    float* ob = g_att + ((size_t)b * S_LEN + q0 + mq) * D_MOD + h * HD;
    #pragma unroll
    for (int nt = 0; nt < 8; nt++) {
        int col = nt * 8 + 2 * t;
        *(float2*)(ob + (size_t)g * D_MOD + col) =
            make_float2(o[nt][0] * inv0, o[nt][1] * inv0);
        *(float2*)(ob + (size_t)(g + 8) * D_MOD + col) =
            make_float2(o[nt][2] * inv1, o[nt][3] * inv1);
    }
}

// ---------------------------------------------------------------------------
extern "C" void kernel_launch(void* const* d_in, const int* in_sizes, int n_in,
                              void* d_out, int out_size)
{
    const float* x = nullptr;
    const float* w_qkv = nullptr;
    const float* w_out = nullptr;
    for (int i = 0; i < n_in; i++) {
        if (in_sizes[i] == B_SZ * S_LEN * D_MOD) x = (const float*)d_in[i];
        else if (in_sizes[i] == D_MOD * 3 * D_MOD) w_qkv = (const float*)d_in[i];
        else if (in_sizes[i] == D_MOD * D_MOD) w_out = (const float*)d_in[i];
    }
    float* out = (float*)d_out;

    float* qkv_p = nullptr;
    float* att_p = nullptr;
    cudaGetSymbolAddress((void**)&qkv_p, g_qkv);
    cudaGetSymbolAddress((void**)&att_p, g_att);

    // sQ 256 rows + sK 64 + sV 64, stride 68 float2 -> 384*68*8 = 208896 B
    const int attn_smem = (256 + 64 + 64) * QS2 * (int)sizeof(float2);
    cudaFuncSetAttribute(attn_tf32, cudaFuncAttributeMaxDynamicSharedMemorySize, attn_smem);

    // 1) QKV projection: [8192,1024] x [1024,3072]
    gemm_tf32<<<dim3(3 * D_MOD / BN, B_SZ * S_LEN / BM), dim3(256)>>>(
        x, w_qkv, qkv_p, B_SZ * S_LEN, 3 * D_MOD, D_MOD);

    // 2) Attention: (b,h) x 256-query tiles
    attn_tf32<<<dim3(S_LEN / 256, B_SZ * H_CNT), dim3(512), attn_smem>>>();

    // 3) Output projection: [8192,1024] x [1024,1024]
    gemm_tf32<<<dim3(D_MOD / BN, B_SZ * S_LEN / BM), dim3(256)>>>(
        att_p, w_out, out, B_SZ * S_LEN, D_MOD, D_MOD);
}